// round 15
// baseline (speedup 1.0000x reference)
#include <cuda_runtime.h>
#include <math.h>
#include <stdint.h>

// ---------------- problem constants ----------------
#define D_FULL   256
#define NHEAD    4
#define HDIM     64
#define NP       16
#define NM       32
#define NR       2
#define NB       1024
#define NL       128
#define NK       8
#define NNEG     2048
#define NPOS     (NB * NK)        /* 8192 */
#define NW       (NPOS + NNEG)    /* 10240 */
#define NUM_LABELS 131072
#define NF4      20               /* float4 feature groups per head: 4 poly + 16 prf */
#define ROWS     8                /* rows per feature block (Q and W) */
#define GS       4                /* neg splits for G partials */
#define GN       (NNEG / GS)      /* 512 negs per split */

// ---------------- device scratch ----------------
__device__ float  g_raw[(NB + NW) * D_FULL];   // raw rows: Q 0..1023, W 1024..11263
__device__ float4 g_Q4[NHEAD * NF4 * NB];      // query feats  [(h*20+f4)*NB + b]
__device__ float4 g_W4[NHEAD * NF4 * NW];      // W feats      [(h*20+f4)*NW + row]
__device__ float  g_pos[NPOS];
__device__ float4 g_Gpart4[GS * 1024];         // [s][h][p][i4] float4
__device__ float  g_Zneg[NB];

// ---------------- gather kernel: low-reg, high-occupancy, both phases ----------------
__global__ void __launch_bounds__(256) gather_kernel(
    const int* __restrict__ indices, const float* __restrict__ mask,
    const float* __restrict__ etab,
    const int* __restrict__ labels, const int* __restrict__ neg_idx,
    const float* __restrict__ kern)
{
    int t = threadIdx.x;
    if (blockIdx.x < NB) {
        int b = blockIdx.x;
        __shared__ int    s_i[NL];
        __shared__ float  s_m[NL];
        __shared__ float4 s_red[256];
        if (t < NL) { s_i[t] = indices[b * NL + t]; s_m[t] = mask[b * NL + t]; }
        __syncthreads();
        int q4 = t & 63, ls = t >> 6;
        const float4* etab4 = (const float4*)etab;
        float4 a = make_float4(0.f, 0.f, 0.f, 0.f);
        #pragma unroll 8
        for (int l = ls; l < NL; l += 4) {
            float mv = s_m[l];
            float4 e = etab4[(size_t)s_i[l] * (D_FULL / 4) + q4];
            a.x = fmaf(mv, e.x, a.x);
            a.y = fmaf(mv, e.y, a.y);
            a.z = fmaf(mv, e.z, a.z);
            a.w = fmaf(mv, e.w, a.w);
        }
        s_red[t] = a;
        __syncthreads();
        if (t < 64) {
            float4 r0 = s_red[t], r1 = s_red[64 + t], r2 = s_red[128 + t], r3 = s_red[192 + t];
            float4 s = make_float4((r0.x + r1.x) + (r2.x + r3.x),
                                   (r0.y + r1.y) + (r2.y + r3.y),
                                   (r0.z + r1.z) + (r2.z + r3.z),
                                   (r0.w + r1.w) + (r2.w + r3.w));
            ((float4*)g_raw)[b * 64 + t] = s;
        }
    } else {
        int row0 = (blockIdx.x - NB) * 8;
        float v[8];
        #pragma unroll
        for (int rr = 0; rr < 8; rr++) {
            int row = row0 + rr;
            int col = (row < NPOS) ? (labels[row] < 0 ? 0 : labels[row]) : neg_idx[row - NPOS];
            v[rr] = kern[(size_t)t * NUM_LABELS + col];
        }
        #pragma unroll
        for (int rr = 0; rr < 8; rr++)
            g_raw[(size_t)(NB + row0 + rr) * D_FULL + t] = v[rr];
    }
}

// ---------------- unified feature kernel (Q blocks then W blocks) ----------------
// Global safe_normalize cancels under the per-head normalize.
__global__ void __launch_bounds__(256) feat_kernel(
    const float* __restrict__ omega, const float* __restrict__ anchors,
    float s0, float s1, float t0, float t1, float c0, float c1)
{
    __shared__ float  s_xall[ROWS][D_FULL];
    __shared__ float  s_ws[ROWS][8];
    __shared__ float  s_anchT[NP * 68];    // [p][d], padded stride 68
    __shared__ float  s_ainv[NP];
    __shared__ float4 s_out[ROWS * 81];    // padded stride 81
    int t = threadIdx.x;

    bool isW = blockIdx.x >= (NB / ROWS);
    int row0 = isW ? (blockIdx.x - NB / ROWS) * ROWS : blockIdx.x * ROWS;
    int rawbase = isW ? NB + row0 : row0;

    // inline anchor normalization (reference: raw norm, no eps), transposed store
    if (t < NP) {
        float s = 0.f;
        #pragma unroll 8
        for (int d = 0; d < HDIM; d++) {
            float v = anchors[t * HDIM + d];
            s = fmaf(v, v, s);
        }
        s_ainv[t] = 1.f / sqrtf(s);
    }
    __syncthreads();
    #pragma unroll
    for (int k = 0; k < 4; k++) {
        int i = t + k * 256;
        int p = i >> 6, d = i & 63;
        s_anchT[p * 68 + d] = anchors[p * HDIM + d] * s_ainv[p];
    }

    // ---- load rows + per-head norms ----
    float v[ROWS];
    #pragma unroll
    for (int rr = 0; rr < ROWS; rr++) {
        v[rr] = g_raw[(size_t)(rawbase + rr) * D_FULL + t];
        float sq = v[rr] * v[rr];
        #pragma unroll
        for (int o = 16; o; o >>= 1) sq += __shfl_xor_sync(0xffffffffu, sq, o);
        if ((t & 31) == 0) s_ws[rr][t >> 5] = sq;
    }
    __syncthreads();
    {
        int hq = t >> 6;
        #pragma unroll
        for (int rr = 0; rr < ROWS; rr++) {
            float n = sqrtf(s_ws[rr][2 * hq] + s_ws[rr][2 * hq + 1]);
            s_xall[rr][t] = v[rr] / fmaxf(n, 1e-20f);
        }
    }
    __syncthreads();

    // ---- PRF: thread -> (r, hh, m); omega streamed once per block, x via LDS.128 ----
    {
        int r = t >> 7, hh = (t >> 5) & 3, m = t & 31;
        float ss = r ? s1 : s0, tt = r ? t1 : t0, cc = r ? c1 : c0;
        const float* omp = omega + ((size_t)(r * NHEAD + hh) * HDIM) * NM + m;
        float dot[ROWS] = {};
        #pragma unroll
        for (int d4 = 0; d4 < HDIM / 4; d4++) {
            float o0 = __ldg(omp + (4 * d4 + 0) * NM);
            float o1 = __ldg(omp + (4 * d4 + 1) * NM);
            float o2 = __ldg(omp + (4 * d4 + 2) * NM);
            float o3 = __ldg(omp + (4 * d4 + 3) * NM);
            #pragma unroll
            for (int rr = 0; rr < ROWS; rr++) {
                float4 x = ((const float4*)&s_xall[rr][hh * HDIM])[d4];
                dot[rr] = fmaf(x.x, o0, fmaf(x.y, o1, fmaf(x.z, o2, fmaf(x.w, o3, dot[rr]))));
            }
        }
        int fin = 16 + r * NM + m;
        int fo = (hh * NF4 + (fin >> 2)) * 4 + (fin & 3);
        #pragma unroll
        for (int rr = 0; rr < ROWS; rr++) {
            float dd = dot[rr] * 0.125f;                 // omega / sqrt(64)
            float arg = fminf(fmaxf(dd * tt - ss, -20.f), 20.f);
            ((float*)s_out)[rr * 324 + fo] = expf(arg) * cc;
        }
    }

    // ---- poly: 64 (h,p) pairs x 4 row-groups of 2, anchors via LDS.128 ----
    {
        int pp = t & 63, h2 = pp >> 4, p = pp & 15, rg = t >> 6;
        float dpa = 0.f, dpb = 0.f;
        #pragma unroll
        for (int d4 = 0; d4 < HDIM / 4; d4++) {
            float4 av = ((const float4*)&s_anchT[p * 68])[d4];
            float4 xa = ((const float4*)&s_xall[rg * 2 + 0][h2 * HDIM])[d4];
            float4 xb = ((const float4*)&s_xall[rg * 2 + 1][h2 * HDIM])[d4];
            dpa = fmaf(xa.x, av.x, fmaf(xa.y, av.y, fmaf(xa.z, av.z, fmaf(xa.w, av.w, dpa))));
            dpb = fmaf(xb.x, av.x, fmaf(xb.y, av.y, fmaf(xb.z, av.z, fmaf(xb.w, av.w, dpb))));
        }
        int fo = (h2 * NF4 + (p >> 2)) * 4 + (p & 3);
        float da = fminf(fmaxf(dpa, -1.f), 1.f);
        float db = fminf(fmaxf(dpb, -1.f), 1.f);
        ((float*)s_out)[(rg * 2 + 0) * 324 + fo] = da * da * 0.25f;   // proj^2/sqrt(16)
        ((float*)s_out)[(rg * 2 + 1) * 324 + fo] = db * db * 0.25f;
    }
    __syncthreads();

    // ---- flush, coalesced over consecutive rows ----
    #pragma unroll
    for (int k = 0; k < (NF4 * NHEAD * ROWS + 255) / 256; k++) {
        int e = t + k * 256;
        if (e < NHEAD * NF4 * ROWS) {
            int f = e >> 3, rr = e & 7;
            if (isW) g_W4[(size_t)f * NW + row0 + rr] = s_out[rr * 81 + f];
            else     g_Q4[(size_t)f * NB + row0 + rr] = s_out[rr * 81 + f];
        }
    }
}

// ---------------- G partials: grid (4 h, 16 i4, 4 split), 512 negs each ----------------
__global__ void __launch_bounds__(256) gpart_kernel()
{
    __shared__ float  sP[GN * 17];     // [n][p], padded
    __shared__ float4 sR[GN];          // [n] for this block's i4
    int t = threadIdx.x;
    int h = blockIdx.x, i4 = blockIdx.y, s = blockIdx.z;
    int n0 = NPOS + s * GN;

    #pragma unroll
    for (int f4 = 0; f4 < 4; f4++) {
        #pragma unroll
        for (int k = 0; k < 2; k++) {
            int n = t + k * 256;
            float4 v = g_W4[(size_t)(h * NF4 + f4) * NW + n0 + n];
            sP[n * 17 + f4 * 4 + 0] = v.x;
            sP[n * 17 + f4 * 4 + 1] = v.y;
            sP[n * 17 + f4 * 4 + 2] = v.z;
            sP[n * 17 + f4 * 4 + 3] = v.w;
        }
    }
    #pragma unroll
    for (int k = 0; k < 2; k++) {
        int n = t + k * 256;
        sR[n] = g_W4[(size_t)(h * NF4 + 4 + i4) * NW + n0 + n];
    }
    __syncthreads();

    int p = t >> 4, sub = t & 15;
    float4 acc = make_float4(0.f, 0.f, 0.f, 0.f);
    #pragma unroll 4
    for (int n = sub; n < GN; n += 16) {
        float  pv = sP[n * 17 + p];
        float4 rv = sR[n];
        acc.x = fmaf(pv, rv.x, acc.x);
        acc.y = fmaf(pv, rv.y, acc.y);
        acc.z = fmaf(pv, rv.z, acc.z);
        acc.w = fmaf(pv, rv.w, acc.w);
    }
    #pragma unroll
    for (int o = 8; o; o >>= 1) {
        acc.x += __shfl_xor_sync(0xffffffffu, acc.x, o);
        acc.y += __shfl_xor_sync(0xffffffffu, acc.y, o);
        acc.z += __shfl_xor_sync(0xffffffffu, acc.z, o);
        acc.w += __shfl_xor_sync(0xffffffffu, acc.w, o);
    }
    if (sub == 0)
        g_Gpart4[s * 1024 + (h * 16 + p) * 16 + i4] = acc;
}

// ---------------- Z_neg + positives ----------------
__global__ void __launch_bounds__(256) zneg_kernel()
{
    __shared__ float4 sG[64 * 17];     // [(h*16+p)*17 + i4], padded
    int t = threadIdx.x;

    // sum G partials into smem
    for (int j = t; j < 1024; j += 256) {
        float4 a = make_float4(0.f, 0.f, 0.f, 0.f);
        #pragma unroll
        for (int s = 0; s < GS; s++) {
            float4 v = g_Gpart4[s * 1024 + j];
            a.x += v.x; a.y += v.y; a.z += v.z; a.w += v.w;
        }
        sG[(j >> 4) * 17 + (j & 15)] = a;
    }

    // positives: this block covers pos rows [blockIdx.x*64, +64); thread=(row,h)
    {
        int row = blockIdx.x * 64 + (t >> 2);
        int h = t & 3;
        int q = row >> 3;
        float dP = 0.f;
        #pragma unroll
        for (int f4 = 0; f4 < 4; f4++) {
            float4 w  = g_W4[(size_t)(h * NF4 + f4) * NW + row];
            float4 qv = g_Q4[(size_t)(h * NF4 + f4) * NB + q];
            dP = fmaf(qv.x, w.x, fmaf(qv.y, w.y, fmaf(qv.z, w.z, fmaf(qv.w, w.w, dP))));
        }
        float dR = 0.f;
        #pragma unroll
        for (int f4 = 4; f4 < NF4; f4++) {
            float4 w  = g_W4[(size_t)(h * NF4 + f4) * NW + row];
            float4 qv = g_Q4[(size_t)(h * NF4 + f4) * NB + q];
            dR = fmaf(qv.x, w.x, fmaf(qv.y, w.y, fmaf(qv.z, w.z, fmaf(qv.w, w.w, dR))));
        }
        float c = dP * dR;
        c += __shfl_xor_sync(0xffffffffu, c, 1);
        c += __shfl_xor_sync(0xffffffffu, c, 2);
        if (h == 0) g_pos[row] = c;
    }
    __syncthreads();

    // Z_neg contraction: warp per query
    int b = blockIdx.x * 8 + (t >> 5);
    int lane = t & 31;
    float acc = 0.f;
    #pragma unroll
    for (int half = 0; half < 2; half++) {
        int e = lane + 32 * half;      // 0..63 -> (h,p)
        int h = e >> 4, p = e & 15;
        float ta = 0.f, tb = 0.f;
        #pragma unroll 8
        for (int i4 = 0; i4 < 16; i4++) {
            float4 qv = g_Q4[(size_t)(h * NF4 + 4 + i4) * NB + b];
            float4 gv = sG[(h * 16 + p) * 17 + i4];
            ta = fmaf(qv.x, gv.x, fmaf(qv.y, gv.y, ta));
            tb = fmaf(qv.z, gv.z, fmaf(qv.w, gv.w, tb));
        }
        float pq = ((const float*)g_Q4)[((size_t)(h * NF4 + (p >> 2)) * NB + b) * 4 + (p & 3)];
        acc = fmaf(pq, ta + tb, acc);
    }
    #pragma unroll
    for (int o = 16; o; o >>= 1) acc += __shfl_xor_sync(0xffffffffu, acc, o);
    if (lane == 0) g_Zneg[b] = acc;
}

// ---------------- final loss reduction ----------------
__global__ void __launch_bounds__(1024) loss_kernel(const float* __restrict__ label_mask,
                                                    float* __restrict__ out)
{
    int t = threadIdx.x;  // t == b
    // Z_b = Z_neg + sum pos + 2056*1e-8  (logsumexp(log x) == log(sum x))
    float Z = g_Zneg[t] + 2056.f * 1e-8f;
    float ps[NK];
    #pragma unroll
    for (int k = 0; k < NK; k++) { ps[k] = g_pos[t * NK + k]; Z += ps[k]; }
    float lz = logf(Z);
    float num = 0.f, den = 0.f;
    #pragma unroll
    for (int k = 0; k < NK; k++) {
        float lm = label_mask[t * NK + k];
        float p  = ps[k] + 1e-8f;
        num += lm * (logf(fmaxf(p, 1e-8f)) - lz);
        den += lm;
    }
    __shared__ float sn[32], sd[32];
    #pragma unroll
    for (int o = 16; o; o >>= 1) {
        num += __shfl_xor_sync(0xffffffffu, num, o);
        den += __shfl_xor_sync(0xffffffffu, den, o);
    }
    if ((t & 31) == 0) { sn[t >> 5] = num; sd[t >> 5] = den; }
    __syncthreads();
    if (t < 32) {
        num = sn[t]; den = sd[t];
        #pragma unroll
        for (int o = 16; o; o >>= 1) {
            num += __shfl_xor_sync(0xffffffffu, num, o);
            den += __shfl_xor_sync(0xffffffffu, den, o);
        }
        if (t == 0) out[0] = -num / (den + 1e-6f);
    }
}

// ---------------- launch ----------------
extern "C" void kernel_launch(void* const* d_in, const int* in_sizes, int n_in,
                              void* d_out, int out_size)
{
    const int*   indices    = (const int*)  d_in[0];
    const float* mask       = (const float*)d_in[1];
    const int*   labels     = (const int*)  d_in[2];
    const float* label_mask = (const float*)d_in[3];
    const int*   neg_idx    = (const int*)  d_in[4];
    const float* etab       = (const float*)d_in[5];
    const float* kern       = (const float*)d_in[6];
    const float* omega      = (const float*)d_in[7];
    const float* anchors    = (const float*)d_in[8];
    float* out = (float*)d_out;

    const double Cc = 2.0 + 1e-6;
    const double r2 = 1.4142135623730951;
    float s0 = (float)((2.0 - r2) / Cc);
    float s1 = (float)((2.0 + r2) / Cc);
    float t0 = sqrtf(2.0f * s0);
    float t1 = sqrtf(2.0f * s1);
    float w0 = (float)(((2.0 + r2) / 4.0) / Cc);
    float w1 = (float)(((2.0 - r2) / 4.0) / Cc);
    float invM = 1.0f / sqrtf(32.0f + 1e-6f);
    float c0 = sqrtf(fmaxf(w0, 1e-6f)) * invM;
    float c1 = sqrtf(fmaxf(w1, 1e-6f)) * invM;

    gather_kernel<<<NB + NW / 8, 256>>>(indices, mask, etab, labels, neg_idx, kern);
    feat_kernel<<<NB / ROWS + NW / ROWS, 256>>>(omega, anchors, s0, s1, t0, t1, c0, c1);
    {
        dim3 grid(NHEAD, 16, GS);
        gpart_kernel<<<grid, 256>>>();
    }
    zneg_kernel<<<NB / 8, 256>>>();
    loss_kernel<<<1, NB>>>(label_mask, out);
}

// round 16
// speedup vs baseline: 1.1769x; 1.1769x over previous
#include <cuda_runtime.h>
#include <math.h>
#include <stdint.h>

// ---------------- problem constants ----------------
#define D_FULL   256
#define NHEAD    4
#define HDIM     64
#define NP       16
#define NM       32
#define NR       2
#define NB       1024
#define NL       128
#define NK       8
#define NNEG     2048
#define NPOS     (NB * NK)        /* 8192 */
#define NW       (NPOS + NNEG)    /* 10240 */
#define NUM_LABELS 131072
#define NF4      20               /* float4 feature groups per head: 4 poly + 16 prf */
#define WROWS    8                /* rows per W feature block (== NK) */
#define QROWS    4                /* rows per Q feature block */
#define GS       4                /* neg splits for G partials */
#define GN       (NNEG / GS)      /* 512 negs per split */

// ---------------- device scratch ----------------
__device__ float  g_raw[(NB + NW) * D_FULL];   // raw rows: Q 0..1023, W 1024..11263
__device__ float4 g_Q4[NHEAD * NF4 * NB];      // query feats  [(h*20+f4)*NB + b]
__device__ float4 g_W4[NHEAD * NF4 * NW];      // W feats      [(h*20+f4)*NW + row]
__device__ float  g_pos[NPOS];
__device__ float4 g_Gpart4[GS * 1024];         // [s][(h*16+p)*16+i4]
__device__ float  g_Zneg[NB];

// ---------------- gather kernel: low-reg, high-occupancy, both phases ----------------
__global__ void __launch_bounds__(256) gather_kernel(
    const int* __restrict__ indices, const float* __restrict__ mask,
    const float* __restrict__ etab,
    const int* __restrict__ labels, const int* __restrict__ neg_idx,
    const float* __restrict__ kern)
{
    int t = threadIdx.x;
    if (blockIdx.x < NB) {
        int b = blockIdx.x;
        __shared__ int    s_i[NL];
        __shared__ float  s_m[NL];
        __shared__ float4 s_red[256];
        if (t < NL) { s_i[t] = indices[b * NL + t]; s_m[t] = mask[b * NL + t]; }
        __syncthreads();
        int q4 = t & 63, ls = t >> 6;
        const float4* etab4 = (const float4*)etab;
        float4 a = make_float4(0.f, 0.f, 0.f, 0.f);
        #pragma unroll 8
        for (int l = ls; l < NL; l += 4) {
            float mv = s_m[l];
            float4 e = etab4[(size_t)s_i[l] * (D_FULL / 4) + q4];
            a.x = fmaf(mv, e.x, a.x);
            a.y = fmaf(mv, e.y, a.y);
            a.z = fmaf(mv, e.z, a.z);
            a.w = fmaf(mv, e.w, a.w);
        }
        s_red[t] = a;
        __syncthreads();
        if (t < 64) {
            float4 r0 = s_red[t], r1 = s_red[64 + t], r2 = s_red[128 + t], r3 = s_red[192 + t];
            float4 s = make_float4((r0.x + r1.x) + (r2.x + r3.x),
                                   (r0.y + r1.y) + (r2.y + r3.y),
                                   (r0.z + r1.z) + (r2.z + r3.z),
                                   (r0.w + r1.w) + (r2.w + r3.w));
            ((float4*)g_raw)[b * 64 + t] = s;
        }
    } else {
        int row0 = (blockIdx.x - NB) * 8;
        float v[8];
        #pragma unroll
        for (int rr = 0; rr < 8; rr++) {
            int row = row0 + rr;
            int col = (row < NPOS) ? (labels[row] < 0 ? 0 : labels[row]) : neg_idx[row - NPOS];
            v[rr] = kern[(size_t)t * NUM_LABELS + col];
        }
        #pragma unroll
        for (int rr = 0; rr < 8; rr++)
            g_raw[(size_t)(NB + row0 + rr) * D_FULL + t] = v[rr];
    }
}

// ---------------- feature kernel (templated Q / W-with-pos) ----------------
// Global safe_normalize cancels under the per-head normalize.
template<int ROWS, bool IS_W>
__global__ void __launch_bounds__(256) feat_kernel(
    const float* __restrict__ omega, const float* __restrict__ anchors,
    float s0, float s1, float t0, float t1, float c0, float c1)
{
    __shared__ float  s_xall[ROWS][D_FULL];
    __shared__ float  s_ws[ROWS][8];
    __shared__ float  s_anchT[NP * 68];    // [p][d], padded stride 68
    __shared__ float  s_ainv[NP];
    __shared__ float4 s_out[ROWS * 81];    // padded stride 81
    __shared__ float4 s_qf[IS_W ? 80 : 1];
    int t = threadIdx.x;

    int row0 = blockIdx.x * ROWS;
    int rawbase = IS_W ? NB + row0 : row0;

    // inline anchor normalization (reference: raw norm, no eps), transposed store
    if (t < NP) {
        float s = 0.f;
        #pragma unroll 8
        for (int d = 0; d < HDIM; d++) {
            float v = anchors[t * HDIM + d];
            s = fmaf(v, v, s);
        }
        s_ainv[t] = 1.f / sqrtf(s);
    }
    __syncthreads();
    #pragma unroll
    for (int k = 0; k < 4; k++) {
        int i = t + k * 256;
        int p = i >> 6, d = i & 63;
        s_anchT[p * 68 + d] = anchors[p * HDIM + d] * s_ainv[p];
    }
    if (IS_W && row0 < NPOS && t < 80) s_qf[t] = g_Q4[(size_t)t * NB + (row0 >> 3)];

    // ---- load rows + per-head norms ----
    float v[ROWS];
    #pragma unroll
    for (int rr = 0; rr < ROWS; rr++) {
        v[rr] = g_raw[(size_t)(rawbase + rr) * D_FULL + t];
        float sq = v[rr] * v[rr];
        #pragma unroll
        for (int o = 16; o; o >>= 1) sq += __shfl_xor_sync(0xffffffffu, sq, o);
        if ((t & 31) == 0) s_ws[rr][t >> 5] = sq;
    }
    __syncthreads();
    {
        int hq = t >> 6;
        #pragma unroll
        for (int rr = 0; rr < ROWS; rr++) {
            float n = sqrtf(s_ws[rr][2 * hq] + s_ws[rr][2 * hq + 1]);
            s_xall[rr][t] = v[rr] / fmaxf(n, 1e-20f);
        }
    }
    __syncthreads();

    // ---- PRF: thread -> (r, hh, m); omega streamed once per block, x via LDS.128 ----
    {
        int r = t >> 7, hh = (t >> 5) & 3, m = t & 31;
        float ss = r ? s1 : s0, tt = r ? t1 : t0, cc = r ? c1 : c0;
        const float* omp = omega + ((size_t)(r * NHEAD + hh) * HDIM) * NM + m;
        float dot[ROWS] = {};
        #pragma unroll
        for (int d4 = 0; d4 < HDIM / 4; d4++) {
            float o0 = __ldg(omp + (4 * d4 + 0) * NM);
            float o1 = __ldg(omp + (4 * d4 + 1) * NM);
            float o2 = __ldg(omp + (4 * d4 + 2) * NM);
            float o3 = __ldg(omp + (4 * d4 + 3) * NM);
            #pragma unroll
            for (int rr = 0; rr < ROWS; rr++) {
                float4 x = ((const float4*)&s_xall[rr][hh * HDIM])[d4];
                dot[rr] = fmaf(x.x, o0, fmaf(x.y, o1, fmaf(x.z, o2, fmaf(x.w, o3, dot[rr]))));
            }
        }
        int fin = 16 + r * NM + m;
        int fo = (hh * NF4 + (fin >> 2)) * 4 + (fin & 3);
        #pragma unroll
        for (int rr = 0; rr < ROWS; rr++) {
            float dd = dot[rr] * 0.125f;                 // omega / sqrt(64)
            float arg = fminf(fmaxf(dd * tt - ss, -20.f), 20.f);
            ((float*)s_out)[rr * 324 + fo] = expf(arg) * cc;
        }
    }

    // ---- poly: 64 (h,p) pairs x 4 row-groups, anchors via LDS.128 ----
    {
        constexpr int RG = (ROWS + 3) / 4;
        int pp = t & 63, h2 = pp >> 4, p = pp & 15, rg = t >> 6;
        float dp[RG] = {};
        #pragma unroll
        for (int d4 = 0; d4 < HDIM / 4; d4++) {
            float4 av = ((const float4*)&s_anchT[p * 68])[d4];
            #pragma unroll
            for (int j = 0; j < RG; j++) {
                int rr = rg * RG + j;
                if (rr < ROWS) {
                    float4 x = ((const float4*)&s_xall[rr][h2 * HDIM])[d4];
                    dp[j] = fmaf(x.x, av.x, fmaf(x.y, av.y, fmaf(x.z, av.z, fmaf(x.w, av.w, dp[j]))));
                }
            }
        }
        int fo = (h2 * NF4 + (p >> 2)) * 4 + (p & 3);
        #pragma unroll
        for (int j = 0; j < RG; j++) {
            int rr = rg * RG + j;
            if (rr < ROWS) {
                float d2 = fminf(fmaxf(dp[j], -1.f), 1.f);
                ((float*)s_out)[rr * 324 + fo] = d2 * d2 * 0.25f;  // proj^2/sqrt(16)
            }
        }
    }
    __syncthreads();

    // ---- flush, coalesced over consecutive rows ----
    #pragma unroll
    for (int k = 0; k < (NF4 * NHEAD * ROWS + 255) / 256; k++) {
        int e = t + k * 256;
        if (e < NHEAD * NF4 * ROWS) {
            int f = e / ROWS, rr = e % ROWS;
            if (IS_W) g_W4[(size_t)f * NW + row0 + rr] = s_out[rr * 81 + f];
            else      g_Q4[(size_t)f * NB + row0 + rr] = s_out[rr * 81 + f];
        }
    }

    // ---- pos fusion: this block's 8 rows are query (row0>>3)'s positives ----
    if (IS_W && row0 < NPOS && t < 32) {
        int rr = t >> 2, h = t & 3;
        const float* so = (const float*)&s_out[rr * 81];
        const float* sq = (const float*)s_qf;
        float dP = 0.f;
        #pragma unroll
        for (int e = 0; e < 16; e++)
            dP = fmaf(so[(h * NF4) * 4 + e], sq[(h * NF4) * 4 + e], dP);
        float dR = 0.f;
        #pragma unroll
        for (int e = 0; e < 64; e++)
            dR = fmaf(so[(h * NF4 + 4) * 4 + e], sq[(h * NF4 + 4) * 4 + e], dR);
        float c = dP * dR;
        c += __shfl_xor_sync(0xffffffffu, c, 1);
        c += __shfl_xor_sync(0xffffffffu, c, 2);
        if ((t & 3) == 0) g_pos[row0 + rr] = c;
    }
}

// ---------------- G partials: grid (4 h, 16 i4, 4 split), 512 negs each ----------------
__global__ void __launch_bounds__(256) gpart_kernel()
{
    __shared__ float  sP[GN * 17];     // [n][p], padded
    __shared__ float4 sR[GN];          // [n] for this block's i4
    int t = threadIdx.x;
    int h = blockIdx.x, i4 = blockIdx.y, s = blockIdx.z;
    int n0 = NPOS + s * GN;

    #pragma unroll
    for (int f4 = 0; f4 < 4; f4++) {
        #pragma unroll
        for (int k = 0; k < 2; k++) {
            int n = t + k * 256;
            float4 v = g_W4[(size_t)(h * NF4 + f4) * NW + n0 + n];
            sP[n * 17 + f4 * 4 + 0] = v.x;
            sP[n * 17 + f4 * 4 + 1] = v.y;
            sP[n * 17 + f4 * 4 + 2] = v.z;
            sP[n * 17 + f4 * 4 + 3] = v.w;
        }
    }
    #pragma unroll
    for (int k = 0; k < 2; k++) {
        int n = t + k * 256;
        sR[n] = g_W4[(size_t)(h * NF4 + 4 + i4) * NW + n0 + n];
    }
    __syncthreads();

    int p = t >> 4, sub = t & 15;
    float4 acc = make_float4(0.f, 0.f, 0.f, 0.f);
    #pragma unroll 4
    for (int n = sub; n < GN; n += 16) {
        float  pv = sP[n * 17 + p];
        float4 rv = sR[n];
        acc.x = fmaf(pv, rv.x, acc.x);
        acc.y = fmaf(pv, rv.y, acc.y);
        acc.z = fmaf(pv, rv.z, acc.z);
        acc.w = fmaf(pv, rv.w, acc.w);
    }
    #pragma unroll
    for (int o = 8; o; o >>= 1) {
        acc.x += __shfl_xor_sync(0xffffffffu, acc.x, o);
        acc.y += __shfl_xor_sync(0xffffffffu, acc.y, o);
        acc.z += __shfl_xor_sync(0xffffffffu, acc.z, o);
        acc.w += __shfl_xor_sync(0xffffffffu, acc.w, o);
    }
    if (sub == 0)
        g_Gpart4[s * 1024 + (h * 16 + p) * 16 + i4] = acc;
}

// ---------------- Z_neg: sum G partials in smem, then warp-per-query contraction ----------------
__global__ void __launch_bounds__(256) zneg_kernel()
{
    __shared__ float4 sG[64 * 17];     // [(h*16+p)*17 + i4], padded
    int t = threadIdx.x;

    for (int j = t; j < 1024; j += 256) {
        float4 a = make_float4(0.f, 0.f, 0.f, 0.f);
        #pragma unroll
        for (int s = 0; s < GS; s++) {
            float4 v = g_Gpart4[s * 1024 + j];
            a.x += v.x; a.y += v.y; a.z += v.z; a.w += v.w;
        }
        sG[(j >> 4) * 17 + (j & 15)] = a;
    }
    __syncthreads();

    int b = blockIdx.x * 8 + (t >> 5);
    int lane = t & 31;
    float acc = 0.f;
    #pragma unroll
    for (int half = 0; half < 2; half++) {
        int e = lane + 32 * half;      // 0..63 -> (h,p)
        int h = e >> 4, p = e & 15;
        float ta = 0.f, tb = 0.f;
        #pragma unroll 8
        for (int i4 = 0; i4 < 16; i4++) {
            float4 qv = g_Q4[(size_t)(h * NF4 + 4 + i4) * NB + b];
            float4 gv = sG[(h * 16 + p) * 17 + i4];
            ta = fmaf(qv.x, gv.x, fmaf(qv.y, gv.y, ta));
            tb = fmaf(qv.z, gv.z, fmaf(qv.w, gv.w, tb));
        }
        float pq = ((const float*)g_Q4)[((size_t)(h * NF4 + (p >> 2)) * NB + b) * 4 + (p & 3)];
        acc = fmaf(pq, ta + tb, acc);
    }
    #pragma unroll
    for (int o = 16; o; o >>= 1) acc += __shfl_xor_sync(0xffffffffu, acc, o);
    if (lane == 0) g_Zneg[b] = acc;
}

// ---------------- final loss reduction ----------------
__global__ void __launch_bounds__(1024) loss_kernel(const float* __restrict__ label_mask,
                                                    float* __restrict__ out)
{
    int t = threadIdx.x;  // t == b
    // Z_b = Z_neg + sum pos + 2056*1e-8  (logsumexp(log x) == log(sum x))
    float Z = g_Zneg[t] + 2056.f * 1e-8f;
    float ps[NK];
    #pragma unroll
    for (int k = 0; k < NK; k++) { ps[k] = g_pos[t * NK + k]; Z += ps[k]; }
    float lz = logf(Z);
    float num = 0.f, den = 0.f;
    #pragma unroll
    for (int k = 0; k < NK; k++) {
        float lm = label_mask[t * NK + k];
        float p  = ps[k] + 1e-8f;
        num += lm * (logf(fmaxf(p, 1e-8f)) - lz);
        den += lm;
    }
    __shared__ float sn[32], sd[32];
    #pragma unroll
    for (int o = 16; o; o >>= 1) {
        num += __shfl_xor_sync(0xffffffffu, num, o);
        den += __shfl_xor_sync(0xffffffffu, den, o);
    }
    if ((t & 31) == 0) { sn[t >> 5] = num; sd[t >> 5] = den; }
    __syncthreads();
    if (t < 32) {
        num = sn[t]; den = sd[t];
        #pragma unroll
        for (int o = 16; o; o >>= 1) {
            num += __shfl_xor_sync(0xffffffffu, num, o);
            den += __shfl_xor_sync(0xffffffffu, den, o);
        }
        if (t == 0) out[0] = -num / (den + 1e-6f);
    }
}

// ---------------- launch ----------------
extern "C" void kernel_launch(void* const* d_in, const int* in_sizes, int n_in,
                              void* d_out, int out_size)
{
    const int*   indices    = (const int*)  d_in[0];
    const float* mask       = (const float*)d_in[1];
    const int*   labels     = (const int*)  d_in[2];
    const float* label_mask = (const float*)d_in[3];
    const int*   neg_idx    = (const int*)  d_in[4];
    const float* etab       = (const float*)d_in[5];
    const float* kern       = (const float*)d_in[6];
    const float* omega      = (const float*)d_in[7];
    const float* anchors    = (const float*)d_in[8];
    float* out = (float*)d_out;

    const double Cc = 2.0 + 1e-6;
    const double r2 = 1.4142135623730951;
    float s0 = (float)((2.0 - r2) / Cc);
    float s1 = (float)((2.0 + r2) / Cc);
    float t0 = sqrtf(2.0f * s0);
    float t1 = sqrtf(2.0f * s1);
    float w0 = (float)(((2.0 + r2) / 4.0) / Cc);
    float w1 = (float)(((2.0 - r2) / 4.0) / Cc);
    float invM = 1.0f / sqrtf(32.0f + 1e-6f);
    float c0 = sqrtf(fmaxf(w0, 1e-6f)) * invM;
    float c1 = sqrtf(fmaxf(w1, 1e-6f)) * invM;

    gather_kernel<<<NB + NW / 8, 256>>>(indices, mask, etab, labels, neg_idx, kern);
    feat_kernel<QROWS, false><<<NB / QROWS, 256>>>(omega, anchors, s0, s1, t0, t1, c0, c1);
    feat_kernel<WROWS, true><<<NW / WROWS, 256>>>(omega, anchors, s0, s1, t0, t1, c0, c1);
    {
        dim3 grid(NHEAD, 16, GS);
        gpart_kernel<<<grid, 256>>>();
    }
    zneg_kernel<<<NB / 8, 256>>>();
    loss_kernel<<<1, NB>>>(label_mask, out);
}